// round 1
// baseline (speedup 1.0000x reference)
#include <cuda_runtime.h>
#include <stdint.h>

// ---------------- problem constants ----------------
#define B_   4
#define LT_  1024
#define D_   1024
#define H_   16
#define HD_  64
#define F_   4096
#define MR_  (B_*LT_)     // 4096 rows
#define ZB_  (B_*H_)      // 64 batched attention slices
#define TENSOR_ELEMS (MR_*D_)  // 4194304

// ---------------- scratch (device globals; no allocs allowed) ----------------
__device__ float g_h  [MR_*D_];          // normed activations
__device__ float g_q  [MR_*D_];
__device__ float g_k  [MR_*D_];
__device__ float g_v  [MR_*D_];
__device__ float g_m  [MR_*D_];          // merged attention output
__device__ float g_x1 [MR_*D_];          // attn_x
__device__ float g_x2 [MR_*D_];          // cross_x
__device__ float g_ffn[MR_*F_];          // relu(h@w1)
__device__ float g_S  [67108864];        // [64,1024,1024] scores (256MB)

// ---------------- helpers ----------------
__device__ __forceinline__ float to_tf32(float x){
    uint32_t u; asm("cvt.rna.tf32.f32 %0, %1;" : "=r"(u) : "f"(x));
    return __uint_as_float(u);
}

__device__ __forceinline__ float blockReduceSum(float v){
    __shared__ float red[8];
    int lane = threadIdx.x & 31, w = threadIdx.x >> 5;
    #pragma unroll
    for(int o=16;o>0;o>>=1) v += __shfl_xor_sync(0xffffffffu, v, o);
    if(lane==0) red[w]=v;
    __syncthreads();
    float s = (threadIdx.x < 8) ? red[threadIdx.x] : 0.f;
    if(w==0){
        #pragma unroll
        for(int o=4;o>0;o>>=1) s += __shfl_xor_sync(0xffffffffu, s, o);
        if(lane==0) red[0]=s;
    }
    __syncthreads();
    float out = red[0];
    __syncthreads();
    return out;
}

__device__ __forceinline__ float blockReduceMax(float v){
    __shared__ float red[8];
    int lane = threadIdx.x & 31, w = threadIdx.x >> 5;
    #pragma unroll
    for(int o=16;o>0;o>>=1) v = fmaxf(v, __shfl_xor_sync(0xffffffffu, v, o));
    if(lane==0) red[w]=v;
    __syncthreads();
    float s = (threadIdx.x < 8) ? red[threadIdx.x] : -3.4e38f;
    if(w==0){
        #pragma unroll
        for(int o=4;o>0;o>>=1) s = fmaxf(s, __shfl_xor_sync(0xffffffffu, s, o));
        if(lane==0) red[0]=s;
    }
    __syncthreads();
    float out = red[0];
    __syncthreads();
    return out;
}

// ---------------- RMS norm: one block per row, D=1024 ----------------
__global__ void rmsnorm_k(const float* __restrict__ x, const float* __restrict__ g,
                          float* __restrict__ o){
    int row = blockIdx.x; int tid = threadIdx.x;
    const float4* xr = (const float4*)(x + (size_t)row*D_);
    float4 v = xr[tid];
    float ss = v.x*v.x + v.y*v.y + v.z*v.z + v.w*v.w;
    ss = blockReduceSum(ss);
    float scale = rsqrtf(ss * (1.0f/D_) + 1e-6f);
    float4 gv = ((const float4*)g)[tid];
    float4 r;
    r.x = v.x*scale*gv.x; r.y = v.y*scale*gv.y;
    r.z = v.z*scale*gv.z; r.w = v.w*scale*gv.w;
    ((float4*)(o + (size_t)row*D_))[tid] = r;
}

// ---------------- softmax over rows of length 1024 ----------------
__global__ void softmax_k(float* __restrict__ S){
    size_t row = blockIdx.x;
    float4* r = (float4*)(S + row*(size_t)LT_);
    float4 v = r[threadIdx.x];
    float m = fmaxf(fmaxf(v.x,v.y), fmaxf(v.z,v.w));
    m = blockReduceMax(m);
    float4 e;
    e.x = __expf(v.x - m); e.y = __expf(v.y - m);
    e.z = __expf(v.z - m); e.w = __expf(v.w - m);
    float s = e.x + e.y + e.z + e.w;
    s = blockReduceSum(s);
    float inv = 1.0f / s;
    e.x *= inv; e.y *= inv; e.z *= inv; e.w *= inv;
    r[threadIdx.x] = e;
}

// ---------------- [B*L, H*HD] -> [B,H,L,HD] transpose copy (float4 units) ----------------
__global__ void kvcopy_k(const float4* __restrict__ in, float4* __restrict__ out){
    int idx = blockIdx.x*256 + threadIdx.x;     // 0 .. 1048575
    int hd4 = idx & 15;
    int h   = (idx >> 4) & 15;
    int l   = (idx >> 8) & 1023;
    int b   = idx >> 18;
    out[(((size_t)(b*16 + h)*1024 + l) << 4) + hd4] =
        in[(((size_t)(b*1024 + l)) << 8) + h*16 + hd4];
}

// ---------------- generic batched tf32 tensor-core GEMM ----------------
// C = f( alpha * A @ op(B) + Add ), f = relu or id. BM=128, BK=32 fixed; BN template.
// Batched over blockIdx.z with (b,h) = (z/Hc, z%Hc) and per-operand strides.
template<int BN_, bool TB, bool RELU>
__global__ void __launch_bounds__(256) gemm_tc(
    const float* __restrict__ A,  int lda,  long long sAb, long long sAh,
    const float* __restrict__ Bm, int ldb,  long long sBb, long long sBh,
    float* __restrict__ C,        int ldc,  long long sCb, long long sCh,
    const float* __restrict__ Add,int ldadd,long long sDb, long long sDh,
    int K, float alpha, int Hc)
{
    constexpr int BM = 128, BK = 32;
    constexpr int ASTR = BK + 4;                      // 36
    constexpr int BROWS = TB ? BN_ : BK;
    constexpr int BSTR  = TB ? (BK + 4) : (BN_ + 4);
    constexpr int NT = (BN_/2)/8;                     // n-frag tiles per warp
    constexpr int A_V = (BM*BK)/(256*4);              // 4
    constexpr int B_V = (BROWS*(TB?BK:BN_))/(256*4);  // 4 or 2

    extern __shared__ float sm[];
    float* As = sm;                        // [2][BM][ASTR]
    float* Bs = sm + 2*BM*ASTR;            // [2][BROWS][BSTR]

    const int tid  = threadIdx.x;
    const int lane = tid & 31, warp = tid >> 5;
    const int wm = warp >> 1, wn = warp & 1;          // 4 x 2 warp grid
    const int gid = lane >> 2, tg = lane & 3;

    const int z = blockIdx.z;
    const int hb = z % Hc, bb = z / Hc;
    A  += (size_t)bb*sAb + (size_t)hb*sAh + (size_t)blockIdx.y*BM*lda;
    Bm += (size_t)bb*sBb + (size_t)hb*sBh
        + (TB ? (size_t)blockIdx.x*BN_*ldb : (size_t)blockIdx.x*BN_);
    C  += (size_t)bb*sCb + (size_t)hb*sCh + (size_t)blockIdx.y*BM*ldc + (size_t)blockIdx.x*BN_;
    if (Add) Add += (size_t)bb*sDb + (size_t)hb*sDh
                  + (size_t)blockIdx.y*BM*ldadd + (size_t)blockIdx.x*BN_;

    float acc[2][NT][4];
    #pragma unroll
    for(int i=0;i<2;i++)
        #pragma unroll
        for(int j=0;j<NT;j++)
            #pragma unroll
            for(int e=0;e<4;e++) acc[i][j][e]=0.f;

    float4 stA[A_V], stB[B_V];

    auto loadA = [&](int kt){
        #pragma unroll
        for(int i=0;i<A_V;i++){
            int idx = tid + i*256;
            int r = idx >> 3, c4 = idx & 7;
            stA[i] = *(const float4*)(A + (size_t)r*lda + kt*BK + c4*4);
        }
    };
    auto storeA = [&](int buf){
        #pragma unroll
        for(int i=0;i<A_V;i++){
            int idx = tid + i*256;
            int r = idx >> 3, c4 = idx & 7;
            float4 v = stA[i];
            v.x=to_tf32(v.x); v.y=to_tf32(v.y); v.z=to_tf32(v.z); v.w=to_tf32(v.w);
            *(float4*)(As + ((size_t)buf*BM + r)*ASTR + c4*4) = v;
        }
    };
    auto loadB = [&](int kt){
        #pragma unroll
        for(int i=0;i<B_V;i++){
            int idx = tid + i*256;
            if constexpr (TB){
                int r = idx >> 3, c4 = idx & 7;   // BN_ rows x 8 float4 of K
                stB[i] = *(const float4*)(Bm + (size_t)r*ldb + kt*BK + c4*4);
            } else {
                constexpr int NC4 = BN_/4;
                int r = idx / NC4, c4 = idx % NC4;
                stB[i] = *(const float4*)(Bm + (size_t)(kt*BK + r)*ldb + c4*4);
            }
        }
    };
    auto storeB = [&](int buf){
        #pragma unroll
        for(int i=0;i<B_V;i++){
            int idx = tid + i*256;
            float4 v = stB[i];
            v.x=to_tf32(v.x); v.y=to_tf32(v.y); v.z=to_tf32(v.z); v.w=to_tf32(v.w);
            if constexpr (TB){
                int r = idx >> 3, c4 = idx & 7;
                *(float4*)(Bs + ((size_t)buf*BROWS + r)*BSTR + c4*4) = v;
            } else {
                constexpr int NC4 = BN_/4;
                int r = idx / NC4, c4 = idx % NC4;
                *(float4*)(Bs + ((size_t)buf*BROWS + r)*BSTR + c4*4) = v;
            }
        }
    };
    auto compute = [&](int buf){
        const float* Ab = As + (size_t)buf*BM*ASTR;
        const float* Bb = Bs + (size_t)buf*BROWS*BSTR;
        #pragma unroll
        for(int ks=0; ks<BK/8; ks++){
            const int k = ks*8;
            uint32_t af[2][4];
            #pragma unroll
            for(int mt=0; mt<2; mt++){
                int row = wm*32 + mt*16;
                af[mt][0] = __float_as_uint(Ab[(row+gid  )*ASTR + k+tg  ]);
                af[mt][1] = __float_as_uint(Ab[(row+gid+8)*ASTR + k+tg  ]);
                af[mt][2] = __float_as_uint(Ab[(row+gid  )*ASTR + k+tg+4]);
                af[mt][3] = __float_as_uint(Ab[(row+gid+8)*ASTR + k+tg+4]);
            }
            uint32_t bf[NT][2];
            #pragma unroll
            for(int nt=0; nt<NT; nt++){
                int col = wn*(BN_/2) + nt*8;
                if constexpr (TB){
                    bf[nt][0] = __float_as_uint(Bb[(col+gid)*BSTR + k+tg  ]);
                    bf[nt][1] = __float_as_uint(Bb[(col+gid)*BSTR + k+tg+4]);
                } else {
                    bf[nt][0] = __float_as_uint(Bb[(k+tg  )*BSTR + col+gid]);
                    bf[nt][1] = __float_as_uint(Bb[(k+tg+4)*BSTR + col+gid]);
                }
            }
            #pragma unroll
            for(int mt=0; mt<2; mt++)
                #pragma unroll
                for(int nt=0; nt<NT; nt++){
                    asm volatile(
                        "mma.sync.aligned.m16n8k8.row.col.f32.tf32.tf32.f32 "
                        "{%0,%1,%2,%3}, {%4,%5,%6,%7}, {%8,%9}, {%0,%1,%2,%3};\n"
                        : "+f"(acc[mt][nt][0]), "+f"(acc[mt][nt][1]),
                          "+f"(acc[mt][nt][2]), "+f"(acc[mt][nt][3])
                        : "r"(af[mt][0]), "r"(af[mt][1]), "r"(af[mt][2]), "r"(af[mt][3]),
                          "r"(bf[nt][0]), "r"(bf[nt][1]));
                }
        }
    };

    const int nT = K / BK;
    loadA(0); loadB(0);
    storeA(0); storeB(0);
    __syncthreads();
    for(int t=0; t<nT; t++){
        const int cur = t & 1;
        if (t+1 < nT){ loadA(t+1); loadB(t+1); }
        compute(cur);
        if (t+1 < nT){ storeA(cur^1); storeB(cur^1); }
        __syncthreads();
    }

    // epilogue
    #pragma unroll
    for(int mt=0; mt<2; mt++)
        #pragma unroll
        for(int nt=0; nt<NT; nt++){
            int row0 = wm*32 + mt*16 + gid;
            int col0 = wn*(BN_/2) + nt*8 + tg*2;
            #pragma unroll
            for(int half=0; half<2; half++){
                int r = row0 + half*8;
                float v0 = alpha*acc[mt][nt][half*2+0];
                float v1 = alpha*acc[mt][nt][half*2+1];
                if (Add){
                    v0 += Add[(size_t)r*ldadd + col0];
                    v1 += Add[(size_t)r*ldadd + col0 + 1];
                }
                if (RELU){ v0 = fmaxf(v0,0.f); v1 = fmaxf(v1,0.f); }
                *(float2*)(C + (size_t)r*ldc + col0) = make_float2(v0, v1);
            }
        }
}

// ---------------- host-side helpers ----------------
static constexpr int smem_bytes(int BN, bool TB){
    int brows = TB ? BN : 32;
    int bstr  = TB ? 36 : BN + 4;
    return (2*128*36 + 2*brows*bstr)*4;
}

static void gemm_nn(const float* A, const float* B, float* C,
                    int M, int N, int K, int lda, int ldb, int ldc,
                    const float* Add, int ldadd, float alpha, bool relu){
    dim3 g(N/128, M/128, 1);
    if (relu)
        gemm_tc<128,false,true ><<<g,256,smem_bytes(128,false)>>>(
            A,lda,0,0, B,ldb,0,0, C,ldc,0,0, Add,ldadd,0,0, K,alpha,1);
    else
        gemm_tc<128,false,false><<<g,256,smem_bytes(128,false)>>>(
            A,lda,0,0, B,ldb,0,0, C,ldc,0,0, Add,ldadd,0,0, K,alpha,1);
}

extern "C" void kernel_launch(void* const* d_in, const int* in_sizes, int n_in,
                              void* d_out, int out_size)
{
    const float* x      = (const float*)d_in[0];
    const float* memin  = (const float*)d_in[1];
    const float* pos    = (const float*)d_in[2];
    const float* causal = (const float*)d_in[3];
    const float* gsa    = (const float*)d_in[4];
    const float* wq_s   = (const float*)d_in[5];
    const float* wk_s   = (const float*)d_in[6];
    const float* wv_s   = (const float*)d_in[7];
    const float* wo_s   = (const float*)d_in[8];
    const float* gca    = (const float*)d_in[9];
    const float* wq_c   = (const float*)d_in[10];
    const float* wk_c   = (const float*)d_in[11];
    const float* wv_c   = (const float*)d_in[12];
    const float* wo_c   = (const float*)d_in[13];
    const float* gm     = (const float*)d_in[14];
    const float* w1     = (const float*)d_in[15];
    const float* w2     = (const float*)d_in[16];

    float* out     = (float*)d_out;
    float* out_mlp = out;
    float* out_ks  = out + (size_t)TENSOR_ELEMS;
    float* out_vs  = out + (size_t)TENSOR_ELEMS*2;
    float* out_kc  = out + (size_t)TENSOR_ELEMS*3;
    float* out_vc  = out + (size_t)TENSOR_ELEMS*4;

    float *h,*q,*k,*v,*m,*x1,*x2,*ffn,*S;
    cudaGetSymbolAddress((void**)&h,   g_h);
    cudaGetSymbolAddress((void**)&q,   g_q);
    cudaGetSymbolAddress((void**)&k,   g_k);
    cudaGetSymbolAddress((void**)&v,   g_v);
    cudaGetSymbolAddress((void**)&m,   g_m);
    cudaGetSymbolAddress((void**)&x1,  g_x1);
    cudaGetSymbolAddress((void**)&x2,  g_x2);
    cudaGetSymbolAddress((void**)&ffn, g_ffn);
    cudaGetSymbolAddress((void**)&S,   g_S);

    cudaFuncSetAttribute(gemm_tc<128,false,false>, cudaFuncAttributeMaxDynamicSharedMemorySize, smem_bytes(128,false));
    cudaFuncSetAttribute(gemm_tc<128,false,true >, cudaFuncAttributeMaxDynamicSharedMemorySize, smem_bytes(128,false));
    cudaFuncSetAttribute(gemm_tc<128,true ,false>, cudaFuncAttributeMaxDynamicSharedMemorySize, smem_bytes(128,true));
    cudaFuncSetAttribute(gemm_tc<64 ,false,false>, cudaFuncAttributeMaxDynamicSharedMemorySize, smem_bytes(64,false));

    const long long sLD = (long long)LT_*D_;   // per-batch stride in [B*L, D] views
    const long long sLL = (long long)LT_*LT_;  // per-(b,h) stride in score buffer

    // ============ self-attention block ============
    rmsnorm_k<<<MR_,256>>>(x, gsa, h);
    gemm_nn(h, wq_s, q, MR_, D_, D_, D_, D_, D_, nullptr, 0, 1.0f, false);
    gemm_nn(h, wk_s, k, MR_, D_, D_, D_, D_, D_, nullptr, 0, 1.0f, false);
    gemm_nn(h, wv_s, v, MR_, D_, D_, D_, D_, D_, nullptr, 0, 1.0f, false);
    kvcopy_k<<<4096,256>>>((const float4*)k, (float4*)out_ks);
    kvcopy_k<<<4096,256>>>((const float4*)v, (float4*)out_vs);

    {   // scores: S = q @ k^T / 8 + causal   (batched over 64 (b,h) slices)
        dim3 g(LT_/128, LT_/128, ZB_);
        gemm_tc<128,true,false><<<g,256,smem_bytes(128,true)>>>(
            q, D_, sLD, HD_,
            k, D_, sLD, HD_,
            S, LT_, (long long)H_*sLL, sLL,
            causal, LT_, 0, 0,
            HD_, 0.125f, H_);
    }
    softmax_k<<<ZB_*LT_,256>>>(S);
    {   // attn = P @ V  -> merged [B*L, D] layout
        dim3 g(1, LT_/128, ZB_);
        gemm_tc<64,false,false><<<g,256,smem_bytes(64,false)>>>(
            S, LT_, (long long)H_*sLL, sLL,
            v, D_, sLD, HD_,
            m, D_, sLD, HD_,
            nullptr, 0, 0, 0,
            LT_, 1.0f, H_);
    }
    // attn_x = attn @ wo_s + x
    gemm_nn(m, wo_s, x1, MR_, D_, D_, D_, D_, D_, x, D_, 1.0f, false);

    // ============ cross-attention block ============
    rmsnorm_k<<<MR_,256>>>(x1, gca, h);
    gemm_nn(h,     wq_c, q, MR_, D_, D_, D_, D_, D_, nullptr, 0, 1.0f, false);
    gemm_nn(memin, wk_c, k, MR_, D_, D_, D_, D_, D_, nullptr, 0, 1.0f, false);
    gemm_nn(memin, wv_c, v, MR_, D_, D_, D_, D_, D_, nullptr, 0, 1.0f, false);
    kvcopy_k<<<4096,256>>>((const float4*)k, (float4*)out_kc);
    kvcopy_k<<<4096,256>>>((const float4*)v, (float4*)out_vc);

    {   // scores: S = q @ k^T / 8 + pos_emb[h]
        dim3 g(LT_/128, LT_/128, ZB_);
        gemm_tc<128,true,false><<<g,256,smem_bytes(128,true)>>>(
            q, D_, sLD, HD_,
            k, D_, sLD, HD_,
            S, LT_, (long long)H_*sLL, sLL,
            pos, LT_, 0, sLL,
            HD_, 0.125f, H_);
    }
    softmax_k<<<ZB_*LT_,256>>>(S);
    {
        dim3 g(1, LT_/128, ZB_);
        gemm_tc<64,false,false><<<g,256,smem_bytes(64,false)>>>(
            S, LT_, (long long)H_*sLL, sLL,
            v, D_, sLD, HD_,
            m, D_, sLD, HD_,
            nullptr, 0, 0, 0,
            LT_, 1.0f, H_);
    }
    // cross_x = attn @ wo_c + attn_x
    gemm_nn(m, wo_c, x2, MR_, D_, D_, D_, D_, D_, x1, D_, 1.0f, false);

    // ============ FFN block ============
    rmsnorm_k<<<MR_,256>>>(x2, gm, h);
    // relu(h @ w1)
    gemm_nn(h, w1, ffn, MR_, F_, D_, D_, F_, F_, nullptr, 0, 1.0f, true);
    // mlp_x = ffn @ w2 + cross_x  -> directly into output
    gemm_nn(ffn, w2, out_mlp, MR_, D_, F_, F_, D_, D_, x2, D_, 1.0f, false);
}

// round 3
// speedup vs baseline: 1.2336x; 1.2336x over previous
#include <cuda_runtime.h>
#include <stdint.h>

// ---------------- problem constants ----------------
#define B_   4
#define LT_  1024
#define D_   1024
#define H_   16
#define HD_  64
#define F_   4096
#define MR_  (B_*LT_)     // 4096 rows
#define TENSOR_ELEMS (MR_*D_)  // 4194304

// ---------------- scratch (device globals; no allocs allowed) ----------------
__device__ float g_h  [MR_*D_];          // normed activations
__device__ float g_q  [MR_*D_];
__device__ float g_k  [MR_*D_];
__device__ float g_v  [MR_*D_];
__device__ float g_m  [MR_*D_];          // merged attention output
__device__ float g_x1 [MR_*D_];          // attn_x
__device__ float g_x2 [MR_*D_];          // cross_x
__device__ float g_ffn[MR_*F_];          // relu(h@w1)

// ---------------- helpers ----------------
__device__ __forceinline__ float to_tf32(float x){
    uint32_t u; asm("cvt.rna.tf32.f32 %0, %1;" : "=r"(u) : "f"(x));
    return __uint_as_float(u);
}
__device__ __forceinline__ uint32_t fu(float x){ return __float_as_uint(x); }

__device__ __forceinline__ void mma8(float* c,
    uint32_t a0, uint32_t a1, uint32_t a2, uint32_t a3,
    uint32_t b0, uint32_t b1){
    asm volatile(
        "mma.sync.aligned.m16n8k8.row.col.f32.tf32.tf32.f32 "
        "{%0,%1,%2,%3}, {%4,%5,%6,%7}, {%8,%9}, {%0,%1,%2,%3};\n"
        : "+f"(c[0]), "+f"(c[1]), "+f"(c[2]), "+f"(c[3])
        : "r"(a0), "r"(a1), "r"(a2), "r"(a3), "r"(b0), "r"(b1));
}

__device__ __forceinline__ float blockReduceSum(float v){
    __shared__ float red[8];
    int lane = threadIdx.x & 31, w = threadIdx.x >> 5;
    #pragma unroll
    for(int o=16;o>0;o>>=1) v += __shfl_xor_sync(0xffffffffu, v, o);
    if(lane==0) red[w]=v;
    __syncthreads();
    float s = (threadIdx.x < 8) ? red[threadIdx.x] : 0.f;
    if(w==0){
        #pragma unroll
        for(int o=4;o>0;o>>=1) s += __shfl_xor_sync(0xffffffffu, s, o);
        if(lane==0) red[0]=s;
    }
    __syncthreads();
    float out = red[0];
    __syncthreads();
    return out;
}

// ---------------- RMS norm ----------------
__global__ void rmsnorm_k(const float* __restrict__ x, const float* __restrict__ g,
                          float* __restrict__ o){
    int row = blockIdx.x; int tid = threadIdx.x;
    const float4* xr = (const float4*)(x + (size_t)row*D_);
    float4 v = xr[tid];
    float ss = v.x*v.x + v.y*v.y + v.z*v.z + v.w*v.w;
    ss = blockReduceSum(ss);
    float scale = rsqrtf(ss * (1.0f/D_) + 1e-6f);
    float4 gv = ((const float4*)g)[tid];
    float4 r;
    r.x = v.x*scale*gv.x; r.y = v.y*scale*gv.y;
    r.z = v.z*scale*gv.z; r.w = v.w*scale*gv.w;
    ((float4*)(o + (size_t)row*D_))[tid] = r;
}

// ---------------- [B*L, H*HD] -> [B,H,L,HD] transpose copy ----------------
__global__ void kvcopy_k(const float4* __restrict__ in, float4* __restrict__ out){
    int idx = blockIdx.x*256 + threadIdx.x;
    int hd4 = idx & 15;
    int h   = (idx >> 4) & 15;
    int l   = (idx >> 8) & 1023;
    int b   = idx >> 18;
    out[(((size_t)(b*16 + h)*1024 + l) << 4) + hd4] =
        in[(((size_t)(b*1024 + l)) << 8) + h*16 + hd4];
}

// =====================================================================
// tf32 tensor-core GEMM, NN, BM=BN=128, BK=32, pair-packed smem (LDS.64)
// C = f(A @ B + Add)
// =====================================================================
#define A_ST  18              // float2 stride of A smem row (16 + 2 pad)
#define A_SZ  (128*A_ST)      // per-buffer float2 count
#define B_ST  132             // float2 stride of B smem row (128 + 4 pad)
#define B_SZ  (16*B_ST)

template<bool RELU>
__global__ void __launch_bounds__(256) gemm_tc(
    const float* __restrict__ A,  int lda,
    const float* __restrict__ Bm, int ldb,
    float* __restrict__ C,        int ldc,
    const float* __restrict__ Add,int ldadd,
    int K)
{
    extern __shared__ float2 sm2[];
    float2* As = sm2;                  // [2][128][A_ST]
    float2* Bs = sm2 + 2*A_SZ;         // [2][16][B_ST]

    const int tid  = threadIdx.x;
    const int lane = tid & 31, warp = tid >> 5;
    const int wm = warp >> 1, wn = warp & 1;
    const int gid = lane >> 2, tg = lane & 3;

    A  += (size_t)blockIdx.y*128*lda;
    Bm += (size_t)blockIdx.x*128;
    C  += (size_t)blockIdx.y*128*ldc + (size_t)blockIdx.x*128;
    if (Add) Add += (size_t)blockIdx.y*128*ldadd + (size_t)blockIdx.x*128;

    float acc[2][8][4];
    #pragma unroll
    for(int i=0;i<2;i++)
        #pragma unroll
        for(int j=0;j<8;j++)
            #pragma unroll
            for(int e=0;e<4;e++) acc[i][j][e]=0.f;

    float4 rA[2][2], rB[2][2];

    auto loadA = [&](int kt){
        #pragma unroll
        for(int i=0;i<2;i++){
            int u = tid + i*256;
            int r = u >> 2, g8 = u & 3;
            const float* s = A + (size_t)r*lda + kt*32 + g8*8;
            rA[i][0] = *(const float4*)s;
            rA[i][1] = *(const float4*)(s+4);
        }
    };
    auto storeA = [&](int buf){
        #pragma unroll
        for(int i=0;i<2;i++){
            int u = tid + i*256;
            int r = u >> 2, g8 = u & 3;
            float4 v = rA[i][0], w = rA[i][1];
            int idx = buf*A_SZ + r*A_ST + g8*4;
            *(float4*)&As[idx]   = make_float4(to_tf32(v.x),to_tf32(w.x),to_tf32(v.y),to_tf32(w.y));
            *(float4*)&As[idx+2] = make_float4(to_tf32(v.z),to_tf32(w.z),to_tf32(v.w),to_tf32(w.w));
        }
    };
    auto loadB = [&](int kt){
        #pragma unroll
        for(int i=0;i<2;i++){
            int u = tid + i*256;
            int pr = u >> 5, c4 = u & 31;
            int g8 = pr >> 2, tw = pr & 3;
            const float* s = Bm + (size_t)(kt*32 + g8*8 + tw)*ldb + c4*4;
            rB[i][0] = *(const float4*)s;
            rB[i][1] = *(const float4*)(s + 4*(size_t)ldb);
        }
    };
    auto storeB = [&](int buf){
        #pragma unroll
        for(int i=0;i<2;i++){
            int u = tid + i*256;
            int pr = u >> 5, c4 = u & 31;
            float4 v = rB[i][0], w = rB[i][1];
            int idx = buf*B_SZ + pr*B_ST + c4*4;
            *(float4*)&Bs[idx]   = make_float4(to_tf32(v.x),to_tf32(w.x),to_tf32(v.y),to_tf32(w.y));
            *(float4*)&Bs[idx+2] = make_float4(to_tf32(v.z),to_tf32(w.z),to_tf32(v.w),to_tf32(w.w));
        }
    };
    auto compute = [&](int buf){
        #pragma unroll
        for(int ks=0; ks<4; ks++){
            const int q = ks*4 + tg;
            float2 a[2][2];
            #pragma unroll
            for(int mt=0; mt<2; mt++){
                int row = wm*32 + mt*16;
                a[mt][0] = As[buf*A_SZ + (row+gid  )*A_ST + q];
                a[mt][1] = As[buf*A_SZ + (row+gid+8)*A_ST + q];
            }
            float2 bb[8];
            #pragma unroll
            for(int nt=0; nt<8; nt++){
                int col = wn*64 + nt*8 + gid;
                bb[nt] = Bs[buf*B_SZ + q*B_ST + col];
            }
            #pragma unroll
            for(int mt=0; mt<2; mt++)
                #pragma unroll
                for(int nt=0; nt<8; nt++)
                    mma8(acc[mt][nt],
                         fu(a[mt][0].x), fu(a[mt][1].x), fu(a[mt][0].y), fu(a[mt][1].y),
                         fu(bb[nt].x), fu(bb[nt].y));
        }
    };

    const int nT = K / 32;
    loadA(0); loadB(0);
    storeA(0); storeB(0);
    __syncthreads();
    for(int t=0; t<nT; t++){
        const int cur = t & 1;
        if (t+1 < nT){ loadA(t+1); loadB(t+1); }
        compute(cur);
        if (t+1 < nT){ storeA(cur^1); storeB(cur^1); }
        __syncthreads();
    }

    #pragma unroll
    for(int mt=0; mt<2; mt++)
        #pragma unroll
        for(int nt=0; nt<8; nt++){
            int row0 = wm*32 + mt*16 + gid;
            int col0 = wn*64 + nt*8 + tg*2;
            #pragma unroll
            for(int half=0; half<2; half++){
                int r = row0 + half*8;
                float v0 = acc[mt][nt][half*2+0];
                float v1 = acc[mt][nt][half*2+1];
                if (Add){
                    v0 += Add[(size_t)r*ldadd + col0];
                    v1 += Add[(size_t)r*ldadd + col0 + 1];
                }
                if (RELU){ v0 = fmaxf(v0,0.f); v1 = fmaxf(v1,0.f); }
                *(float2*)(C + (size_t)r*ldc + col0) = make_float2(v0, v1);
            }
        }
}

// =====================================================================
// Flash attention (tf32): per CTA one (b,h,q-tile of 128). 8 warps x 16 rows.
// S = (Q/8) @ K^T (+bias | causal), online softmax, O += P @ V.
// smem: Qs [128][34] f2 (A-pack k=64), Ks [128][34] f2, Vs [64][68] f2,
//       Ps [128][132] f32.
// =====================================================================
#define Q_ST 34
#define V_ST 68
#define P_ST 132
#define OFF_KS  (128*Q_ST)           // float2 offsets
#define OFF_VS  (2*128*Q_ST)
#define OFF_PS_BYTES ((2*128*Q_ST + 64*V_ST)*8)
#define FLASH_SMEM (OFF_PS_BYTES + 128*P_ST*4)

template<bool CAUSAL>
__global__ void __launch_bounds__(256) flash_k(
    const float* __restrict__ Q, const float* __restrict__ Kg,
    const float* __restrict__ Vg, const float* __restrict__ bias,
    float* __restrict__ O)
{
    extern __shared__ float2 sm2[];
    float2* Qs = sm2;
    float2* Ks = sm2 + OFF_KS;
    float2* Vs = sm2 + OFF_VS;
    float*  Ps = (float*)((char*)sm2 + OFF_PS_BYTES);

    const int tid = threadIdx.x, lane = tid & 31, warp = tid >> 5;
    const int gid = lane >> 2, tg = lane & 3;
    const int qt = blockIdx.x, bh = blockIdx.y;
    const int b = bh >> 4, h = bh & 15;

    const float* Qb = Q  + ((size_t)(b*1024 + qt*128))*D_ + h*64;
    const float* Kb = Kg + ((size_t)b*1024)*D_ + h*64;
    const float* Vb = Vg + ((size_t)b*1024)*D_ + h*64;

    // load Q tile (scaled by 1/8, tf32), A-pack
    #pragma unroll
    for(int i=0;i<4;i++){
        int u = tid + i*256;
        int r = u >> 3, g8 = u & 7;
        const float* s = Qb + (size_t)r*D_ + g8*8;
        float4 v = *(const float4*)s, w = *(const float4*)(s+4);
        int idx = r*Q_ST + g8*4;
        *(float4*)&Qs[idx]   = make_float4(to_tf32(v.x*0.125f),to_tf32(w.x*0.125f),
                                           to_tf32(v.y*0.125f),to_tf32(w.y*0.125f));
        *(float4*)&Qs[idx+2] = make_float4(to_tf32(v.z*0.125f),to_tf32(w.z*0.125f),
                                           to_tf32(v.w*0.125f),to_tf32(w.w*0.125f));
    }

    float m0=-3.4e38f, m1=-3.4e38f, l0=0.f, l1=0.f;
    float accO[8][4];
    #pragma unroll
    for(int i=0;i<8;i++){ accO[i][0]=0;accO[i][1]=0;accO[i][2]=0;accO[i][3]=0; }

    const int wrow = warp*16;
    const int ntiles = CAUSAL ? (qt+1) : 8;

    for(int kt=0; kt<ntiles; kt++){
        const float* Kt = Kb + (size_t)kt*128*D_;
        const float* Vt = Vb + (size_t)kt*128*D_;
        // K tile: A-pack
        #pragma unroll
        for(int i=0;i<4;i++){
            int u = tid + i*256;
            int r = u >> 3, g8 = u & 7;
            const float* s = Kt + (size_t)r*D_ + g8*8;
            float4 v = *(const float4*)s, w = *(const float4*)(s+4);
            int idx = r*Q_ST + g8*4;
            *(float4*)&Ks[idx]   = make_float4(to_tf32(v.x),to_tf32(w.x),to_tf32(v.y),to_tf32(w.y));
            *(float4*)&Ks[idx+2] = make_float4(to_tf32(v.z),to_tf32(w.z),to_tf32(v.w),to_tf32(w.w));
        }
        // V tile: B-pack (pairs over key dim)
        #pragma unroll
        for(int i=0;i<4;i++){
            int u = tid + i*256;
            int pr = u >> 4, c4 = u & 15;
            int g8 = pr >> 2, tw = pr & 3;
            const float* s = Vt + (size_t)(g8*8 + tw)*D_ + c4*4;
            float4 v = *(const float4*)s, w = *(const float4*)(s + 4*(size_t)D_);
            int idx = pr*V_ST + c4*4;
            *(float4*)&Vs[idx]   = make_float4(to_tf32(v.x),to_tf32(w.x),to_tf32(v.y),to_tf32(w.y));
            *(float4*)&Vs[idx+2] = make_float4(to_tf32(v.z),to_tf32(w.z),to_tf32(v.w),to_tf32(w.w));
        }
        __syncthreads();

        // ---- S = Qs @ Ks^T ----
        float s[16][4];
        #pragma unroll
        for(int nt=0;nt<16;nt++){ s[nt][0]=0;s[nt][1]=0;s[nt][2]=0;s[nt][3]=0; }
        #pragma unroll
        for(int ks=0; ks<8; ks++){
            int q = ks*4 + tg;
            float2 a0 = Qs[(wrow+gid  )*Q_ST + q];
            float2 a1 = Qs[(wrow+gid+8)*Q_ST + q];
            uint32_t A0=fu(a0.x), A1=fu(a1.x), A2=fu(a0.y), A3=fu(a1.y);
            #pragma unroll
            for(int nt=0; nt<16; nt++){
                float2 bp = Ks[(nt*8+gid)*Q_ST + q];
                mma8(s[nt], A0, A1, A2, A3, fu(bp.x), fu(bp.y));
            }
        }

        // ---- bias / causal mask ----
        const int gr0 = qt*128 + wrow + gid;
        const int gr1 = gr0 + 8;
        #pragma unroll
        for(int nt=0; nt<16; nt++){
            int gc = kt*128 + nt*8 + tg*2;
            if (CAUSAL){
                if (gc   > gr0) s[nt][0] += -1e9f;
                if (gc+1 > gr0) s[nt][1] += -1e9f;
                if (gc   > gr1) s[nt][2] += -1e9f;
                if (gc+1 > gr1) s[nt][3] += -1e9f;
            } else {
                const float* bp = bias + ((size_t)h*1024 + gr0)*1024 + gc;
                float2 b0 = *(const float2*)bp;
                float2 b1 = *(const float2*)(bp + 8*1024);
                s[nt][0]+=b0.x; s[nt][1]+=b0.y; s[nt][2]+=b1.x; s[nt][3]+=b1.y;
            }
        }

        // ---- online softmax ----
        float t0=-3.4e38f, t1=-3.4e38f;
        #pragma unroll
        for(int nt=0; nt<16; nt++){
            t0 = fmaxf(t0, fmaxf(s[nt][0], s[nt][1]));
            t1 = fmaxf(t1, fmaxf(s[nt][2], s[nt][3]));
        }
        t0 = fmaxf(t0, __shfl_xor_sync(0xffffffffu, t0, 1));
        t0 = fmaxf(t0, __shfl_xor_sync(0xffffffffu, t0, 2));
        t1 = fmaxf(t1, __shfl_xor_sync(0xffffffffu, t1, 1));
        t1 = fmaxf(t1, __shfl_xor_sync(0xffffffffu, t1, 2));
        float nm0 = fmaxf(m0, t0), nm1 = fmaxf(m1, t1);
        float c0 = __expf(m0 - nm0), c1 = __expf(m1 - nm1);
        float sum0 = 0.f, sum1 = 0.f;
        #pragma unroll
        for(int nt=0; nt<16; nt++){
            float p0 = __expf(s[nt][0]-nm0), p1 = __expf(s[nt][1]-nm0);
            float p2 = __expf(s[nt][2]-nm1), p3 = __expf(s[nt][3]-nm1);
            sum0 += p0+p1; sum1 += p2+p3;
            int c = nt*8 + tg*2;
            *(float2*)&Ps[(wrow+gid  )*P_ST + c] = make_float2(to_tf32(p0), to_tf32(p1));
            *(float2*)&Ps[(wrow+gid+8)*P_ST + c] = make_float2(to_tf32(p2), to_tf32(p3));
        }
        sum0 += __shfl_xor_sync(0xffffffffu, sum0, 1);
        sum0 += __shfl_xor_sync(0xffffffffu, sum0, 2);
        sum1 += __shfl_xor_sync(0xffffffffu, sum1, 1);
        sum1 += __shfl_xor_sync(0xffffffffu, sum1, 2);
        l0 = l0*c0 + sum0; l1 = l1*c1 + sum1;
        m0 = nm0; m1 = nm1;
        #pragma unroll
        for(int nt=0; nt<8; nt++){
            accO[nt][0]*=c0; accO[nt][1]*=c0; accO[nt][2]*=c1; accO[nt][3]*=c1;
        }
        __syncwarp();

        // ---- O += P @ V ----
        #pragma unroll
        for(int ks=0; ks<16; ks++){
            int k8 = ks*8;
            const float* pr0 = &Ps[(wrow+gid  )*P_ST + k8];
            const float* pr1 = &Ps[(wrow+gid+8)*P_ST + k8];
            uint32_t A0 = fu(pr0[tg]),   A1 = fu(pr1[tg]);
            uint32_t A2 = fu(pr0[tg+4]), A3 = fu(pr1[tg+4]);
            #pragma unroll
            for(int nt=0; nt<8; nt++){
                float2 bp = Vs[(ks*4+tg)*V_ST + nt*8 + gid];
                mma8(accO[nt], A0, A1, A2, A3, fu(bp.x), fu(bp.y));
            }
        }
        __syncthreads();
    }

    // ---- epilogue: O / l ----
    float inv0 = 1.f/l0, inv1 = 1.f/l1;
    int gq0 = b*1024 + qt*128 + wrow + gid;
    #pragma unroll
    for(int nt=0; nt<8; nt++){
        int c = h*64 + nt*8 + tg*2;
        *(float2*)(O + (size_t)gq0*D_ + c) =
            make_float2(accO[nt][0]*inv0, accO[nt][1]*inv0);
        *(float2*)(O + (size_t)(gq0+8)*D_ + c) =
            make_float2(accO[nt][2]*inv1, accO[nt][3]*inv1);
    }
}

// ---------------- host side ----------------
static const int GEMM_SMEM = (2*A_SZ + 2*B_SZ)*8;

static void gemm_nn(const float* A, const float* B, float* C,
                    int M, int N, int K, int lda, int ldb, int ldc,
                    const float* Add, int ldadd, bool relu){
    dim3 g(N/128, M/128, 1);
    if (relu)
        gemm_tc<true ><<<g,256,GEMM_SMEM>>>(A,lda,B,ldb,C,ldc,Add,ldadd,K);
    else
        gemm_tc<false><<<g,256,GEMM_SMEM>>>(A,lda,B,ldb,C,ldc,Add,ldadd,K);
}

extern "C" void kernel_launch(void* const* d_in, const int* in_sizes, int n_in,
                              void* d_out, int out_size)
{
    const float* x      = (const float*)d_in[0];
    const float* memin  = (const float*)d_in[1];
    const float* pos    = (const float*)d_in[2];
    // d_in[3] = causal mask (unused; computed analytically)
    const float* gsa    = (const float*)d_in[4];
    const float* wq_s   = (const float*)d_in[5];
    const float* wk_s   = (const float*)d_in[6];
    const float* wv_s   = (const float*)d_in[7];
    const float* wo_s   = (const float*)d_in[8];
    const float* gca    = (const float*)d_in[9];
    const float* wq_c   = (const float*)d_in[10];
    const float* wk_c   = (const float*)d_in[11];
    const float* wv_c   = (const float*)d_in[12];
    const float* wo_c   = (const float*)d_in[13];
    const float* gm     = (const float*)d_in[14];
    const float* w1     = (const float*)d_in[15];
    const float* w2     = (const float*)d_in[16];

    float* out     = (float*)d_out;
    float* out_mlp = out;
    float* out_ks  = out + (size_t)TENSOR_ELEMS;
    float* out_vs  = out + (size_t)TENSOR_ELEMS*2;
    float* out_kc  = out + (size_t)TENSOR_ELEMS*3;
    float* out_vc  = out + (size_t)TENSOR_ELEMS*4;

    float *h,*q,*k,*v,*m,*x1,*x2,*ffn;
    cudaGetSymbolAddress((void**)&h,   g_h);
    cudaGetSymbolAddress((void**)&q,   g_q);
    cudaGetSymbolAddress((void**)&k,   g_k);
    cudaGetSymbolAddress((void**)&v,   g_v);
    cudaGetSymbolAddress((void**)&m,   g_m);
    cudaGetSymbolAddress((void**)&x1,  g_x1);
    cudaGetSymbolAddress((void**)&x2,  g_x2);
    cudaGetSymbolAddress((void**)&ffn, g_ffn);

    cudaFuncSetAttribute(gemm_tc<false>, cudaFuncAttributeMaxDynamicSharedMemorySize, GEMM_SMEM);
    cudaFuncSetAttribute(gemm_tc<true >, cudaFuncAttributeMaxDynamicSharedMemorySize, GEMM_SMEM);
    cudaFuncSetAttribute(flash_k<true >, cudaFuncAttributeMaxDynamicSharedMemorySize, FLASH_SMEM);
    cudaFuncSetAttribute(flash_k<false>, cudaFuncAttributeMaxDynamicSharedMemorySize, FLASH_SMEM);

    // ============ self-attention block ============
    rmsnorm_k<<<MR_,256>>>(x, gsa, h);
    gemm_nn(h, wq_s, q, MR_, D_, D_, D_, D_, D_, nullptr, 0, false);
    gemm_nn(h, wk_s, k, MR_, D_, D_, D_, D_, D_, nullptr, 0, false);
    gemm_nn(h, wv_s, v, MR_, D_, D_, D_, D_, D_, nullptr, 0, false);
    kvcopy_k<<<4096,256>>>((const float4*)k, (float4*)out_ks);
    kvcopy_k<<<4096,256>>>((const float4*)v, (float4*)out_vs);

    flash_k<true><<<dim3(8,64),256,FLASH_SMEM>>>(q, k, v, nullptr, m);

    gemm_nn(m, wo_s, x1, MR_, D_, D_, D_, D_, D_, x, D_, false);

    // ============ cross-attention block ============
    rmsnorm_k<<<MR_,256>>>(x1, gca, h);
    gemm_nn(h,     wq_c, q, MR_, D_, D_, D_, D_, D_, nullptr, 0, false);
    gemm_nn(memin, wk_c, k, MR_, D_, D_, D_, D_, D_, nullptr, 0, false);
    gemm_nn(memin, wv_c, v, MR_, D_, D_, D_, D_, D_, nullptr, 0, false);
    kvcopy_k<<<4096,256>>>((const float4*)k, (float4*)out_kc);
    kvcopy_k<<<4096,256>>>((const float4*)v, (float4*)out_vc);

    flash_k<false><<<dim3(8,64),256,FLASH_SMEM>>>(q, k, v, pos, m);

    gemm_nn(m, wo_c, x2, MR_, D_, D_, D_, D_, D_, x1, D_, false);

    // ============ FFN block ============
    rmsnorm_k<<<MR_,256>>>(x2, gm, h);
    gemm_nn(h, w1, ffn, MR_, F_, D_, D_, F_, F_, nullptr, 0, true);
    gemm_nn(ffn, w2, out_mlp, MR_, D_, F_, F_, D_, D_, x2, D_, false);
}

// round 4
// speedup vs baseline: 1.4988x; 1.2150x over previous
#include <cuda_runtime.h>
#include <stdint.h>

// ---------------- problem constants ----------------
#define B_   4
#define LT_  1024
#define D_   1024
#define H_   16
#define HD_  64
#define F_   4096
#define MR_  (B_*LT_)     // 4096 rows
#define TENSOR_ELEMS (MR_*D_)  // 4194304

// ---------------- scratch (device globals; no allocs allowed) ----------------
__device__ float g_h  [MR_*D_];          // normed activations
__device__ float g_q  [MR_*D_];
__device__ float g_k  [MR_*D_];
__device__ float g_v  [MR_*D_];
__device__ float g_m  [MR_*D_];          // merged attention output
__device__ float g_x1 [MR_*D_];          // attn_x
__device__ float g_x2 [MR_*D_];          // cross_x
__device__ float g_ffn[MR_*F_];          // relu(h@w1)

// ---------------- helpers ----------------
__device__ __forceinline__ float to_tf32(float x){
    uint32_t u; asm("cvt.rna.tf32.f32 %0, %1;" : "=r"(u) : "f"(x));
    return __uint_as_float(u);
}
__device__ __forceinline__ uint32_t fu(float x){ return __float_as_uint(x); }

__device__ __forceinline__ void mma8(float* c,
    uint32_t a0, uint32_t a1, uint32_t a2, uint32_t a3,
    uint32_t b0, uint32_t b1){
    asm volatile(
        "mma.sync.aligned.m16n8k8.row.col.f32.tf32.tf32.f32 "
        "{%0,%1,%2,%3}, {%4,%5,%6,%7}, {%8,%9}, {%0,%1,%2,%3};\n"
        : "+f"(c[0]), "+f"(c[1]), "+f"(c[2]), "+f"(c[3])
        : "r"(a0), "r"(a1), "r"(a2), "r"(a3), "r"(b0), "r"(b1));
}

__device__ __forceinline__ float blockReduceSum(float v){
    __shared__ float red[8];
    int lane = threadIdx.x & 31, w = threadIdx.x >> 5;
    #pragma unroll
    for(int o=16;o>0;o>>=1) v += __shfl_xor_sync(0xffffffffu, v, o);
    if(lane==0) red[w]=v;
    __syncthreads();
    float s = (threadIdx.x < 8) ? red[threadIdx.x] : 0.f;
    if(w==0){
        #pragma unroll
        for(int o=4;o>0;o>>=1) s += __shfl_xor_sync(0xffffffffu, s, o);
        if(lane==0) red[0]=s;
    }
    __syncthreads();
    float out = red[0];
    __syncthreads();
    return out;
}

// ---------------- RMS norm ----------------
__global__ void rmsnorm_k(const float* __restrict__ x, const float* __restrict__ g,
                          float* __restrict__ o){
    int row = blockIdx.x; int tid = threadIdx.x;
    const float4* xr = (const float4*)(x + (size_t)row*D_);
    float4 v = xr[tid];
    float ss = v.x*v.x + v.y*v.y + v.z*v.z + v.w*v.w;
    ss = blockReduceSum(ss);
    float scale = rsqrtf(ss * (1.0f/D_) + 1e-6f);
    float4 gv = ((const float4*)g)[tid];
    float4 r;
    r.x = v.x*scale*gv.x; r.y = v.y*scale*gv.y;
    r.z = v.z*scale*gv.z; r.w = v.w*scale*gv.w;
    ((float4*)(o + (size_t)row*D_))[tid] = r;
}

// ---------------- [B*L, H*HD] -> [B,H,L,HD] transpose copy (x2 batched) ----------------
__global__ void kvcopy2_k(const float4* __restrict__ in0, float4* __restrict__ o0,
                          const float4* __restrict__ in1, float4* __restrict__ o1){
    int idx = blockIdx.x*256 + threadIdx.x;
    const float4* in = blockIdx.y ? in1 : in0;
    float4*      out = blockIdx.y ? o1  : o0;
    int hd4 = idx & 15;
    int h   = (idx >> 4) & 15;
    int l   = (idx >> 8) & 1023;
    int b   = idx >> 18;
    out[(((size_t)(b*16 + h)*1024 + l) << 4) + hd4] =
        in[(((size_t)(b*1024 + l)) << 8) + h*16 + hd4];
}

// =====================================================================
// tf32 tensor-core GEMM, NN. CTA tile 256x128, BK=32, 8 warps (4x2),
// warp tile 64x64. Pair-packed smem (LDS.64 fragment loads), A stride
// padded to 20 float2 (conflict-free). Batched over blockIdx.z (up to 3
// independent A/W/C with identical shapes). C = f(A@W + Add).
// lda = K, ldb = ldc = ldadd = N.
// =====================================================================
#define A_ST  20              // float2 stride of A smem row (16 + 4 pad)
#define A_SZ  (256*A_ST)      // per-buffer float2 count
#define B_ST  132             // float2 stride of B smem row (128 + 4 pad)
#define B_SZ  (16*B_ST)
static const int GEMM_SMEM = (2*A_SZ + 2*B_SZ)*8;

template<bool RELU>
__global__ void __launch_bounds__(256,1) gemm_tc(
    const float* __restrict__ A0, const float* __restrict__ A1, const float* __restrict__ A2,
    const float* __restrict__ W0, const float* __restrict__ W1, const float* __restrict__ W2,
    float* __restrict__ C0, float* __restrict__ C1, float* __restrict__ C2,
    const float* __restrict__ Add,
    int K, int N)
{
    extern __shared__ float2 sm2[];
    float2* As = sm2;                  // [2][256][A_ST]
    float2* Bs = sm2 + 2*A_SZ;         // [2][16][B_ST]

    const int tid  = threadIdx.x;
    const int lane = tid & 31, warp = tid >> 5;
    const int wm = warp & 3, wn = warp >> 2;          // 4 x 2 warp grid
    const int gid = lane >> 2, tg = lane & 3;

    const int z = blockIdx.z;
    const float* A  = (z==0) ? A0 : (z==1) ? A1 : A2;
    const float* Bm = (z==0) ? W0 : (z==1) ? W1 : W2;
    float*       C  = (z==0) ? C0 : (z==1) ? C1 : C2;

    A  += (size_t)blockIdx.y*256*K;
    Bm += (size_t)blockIdx.x*128;
    C  += (size_t)blockIdx.y*256*N + (size_t)blockIdx.x*128;
    if (Add) Add += (size_t)blockIdx.y*256*N + (size_t)blockIdx.x*128;

    float acc[4][8][4];
    #pragma unroll
    for(int i=0;i<4;i++)
        #pragma unroll
        for(int j=0;j<8;j++)
            #pragma unroll
            for(int e=0;e<4;e++) acc[i][j][e]=0.f;

    float4 rA[4][2], rB[2][2];

    auto loadA = [&](int kt){
        #pragma unroll
        for(int i=0;i<4;i++){
            int u = tid + i*256;
            int r = u >> 2, g8 = u & 3;
            const float* s = A + (size_t)r*K + kt*32 + g8*8;
            rA[i][0] = *(const float4*)s;
            rA[i][1] = *(const float4*)(s+4);
        }
    };
    auto storeA = [&](int buf){
        #pragma unroll
        for(int i=0;i<4;i++){
            int u = tid + i*256;
            int r = u >> 2, g8 = u & 3;
            float4 v = rA[i][0], w = rA[i][1];
            int idx = buf*A_SZ + r*A_ST + g8*4;
            *(float4*)&As[idx]   = make_float4(to_tf32(v.x),to_tf32(w.x),to_tf32(v.y),to_tf32(w.y));
            *(float4*)&As[idx+2] = make_float4(to_tf32(v.z),to_tf32(w.z),to_tf32(v.w),to_tf32(w.w));
        }
    };
    auto loadB = [&](int kt){
        #pragma unroll
        for(int i=0;i<2;i++){
            int u = tid + i*256;
            int pr = u >> 5, c4 = u & 31;
            int g8 = pr >> 2, tw = pr & 3;
            const float* s = Bm + (size_t)(kt*32 + g8*8 + tw)*N + c4*4;
            rB[i][0] = *(const float4*)s;
            rB[i][1] = *(const float4*)(s + 4*(size_t)N);
        }
    };
    auto storeB = [&](int buf){
        #pragma unroll
        for(int i=0;i<2;i++){
            int u = tid + i*256;
            int pr = u >> 5, c4 = u & 31;
            float4 v = rB[i][0], w = rB[i][1];
            int idx = buf*B_SZ + pr*B_ST + c4*4;
            *(float4*)&Bs[idx]   = make_float4(to_tf32(v.x),to_tf32(w.x),to_tf32(v.y),to_tf32(w.y));
            *(float4*)&Bs[idx+2] = make_float4(to_tf32(v.z),to_tf32(w.z),to_tf32(v.w),to_tf32(w.w));
        }
    };
    auto compute = [&](int buf){
        #pragma unroll
        for(int ks=0; ks<4; ks++){
            const int q = ks*4 + tg;
            float2 a[4][2];
            #pragma unroll
            for(int mt=0; mt<4; mt++){
                int row = wm*64 + mt*16;
                a[mt][0] = As[buf*A_SZ + (row+gid  )*A_ST + q];
                a[mt][1] = As[buf*A_SZ + (row+gid+8)*A_ST + q];
            }
            float2 bb[8];
            #pragma unroll
            for(int nt=0; nt<8; nt++){
                int col = wn*64 + nt*8 + gid;
                bb[nt] = Bs[buf*B_SZ + q*B_ST + col];
            }
            #pragma unroll
            for(int mt=0; mt<4; mt++)
                #pragma unroll
                for(int nt=0; nt<8; nt++)
                    mma8(acc[mt][nt],
                         fu(a[mt][0].x), fu(a[mt][1].x), fu(a[mt][0].y), fu(a[mt][1].y),
                         fu(bb[nt].x), fu(bb[nt].y));
        }
    };

    const int nT = K / 32;
    loadA(0); loadB(0);
    storeA(0); storeB(0);
    __syncthreads();
    for(int t=0; t<nT; t++){
        const int cur = t & 1;
        if (t+1 < nT){ loadA(t+1); loadB(t+1); }
        compute(cur);
        if (t+1 < nT){ storeA(cur^1); storeB(cur^1); }
        __syncthreads();
    }

    #pragma unroll
    for(int mt=0; mt<4; mt++)
        #pragma unroll
        for(int nt=0; nt<8; nt++){
            int row0 = wm*64 + mt*16 + gid;
            int col0 = wn*64 + nt*8 + tg*2;
            #pragma unroll
            for(int half=0; half<2; half++){
                int r = row0 + half*8;
                float v0 = acc[mt][nt][half*2+0];
                float v1 = acc[mt][nt][half*2+1];
                if (Add){
                    v0 += Add[(size_t)r*N + col0];
                    v1 += Add[(size_t)r*N + col0 + 1];
                }
                if (RELU){ v0 = fmaxf(v0,0.f); v1 = fmaxf(v1,0.f); }
                *(float2*)(C + (size_t)r*N + col0) = make_float2(v0, v1);
            }
        }
}

// =====================================================================
// Flash attention (tf32): per CTA one (b,h,q-tile of 128). 8 warps x 16 rows.
// =====================================================================
#define Q_ST 34
#define V_ST 68
#define P_ST 132
#define OFF_KS  (128*Q_ST)           // float2 offsets
#define OFF_VS  (2*128*Q_ST)
#define OFF_PS_BYTES ((2*128*Q_ST + 64*V_ST)*8)
#define FLASH_SMEM (OFF_PS_BYTES + 128*P_ST*4)

template<bool CAUSAL>
__global__ void __launch_bounds__(256) flash_k(
    const float* __restrict__ Q, const float* __restrict__ Kg,
    const float* __restrict__ Vg, const float* __restrict__ bias,
    float* __restrict__ O)
{
    extern __shared__ float2 sm2[];
    float2* Qs = sm2;
    float2* Ks = sm2 + OFF_KS;
    float2* Vs = sm2 + OFF_VS;
    float*  Ps = (float*)((char*)sm2 + OFF_PS_BYTES);

    const int tid = threadIdx.x, lane = tid & 31, warp = tid >> 5;
    const int gid = lane >> 2, tg = lane & 3;
    const int qt = blockIdx.x, bh = blockIdx.y;
    const int b = bh >> 4, h = bh & 15;

    const float* Qb = Q  + ((size_t)(b*1024 + qt*128))*D_ + h*64;
    const float* Kb = Kg + ((size_t)b*1024)*D_ + h*64;
    const float* Vb = Vg + ((size_t)b*1024)*D_ + h*64;

    #pragma unroll
    for(int i=0;i<4;i++){
        int u = tid + i*256;
        int r = u >> 3, g8 = u & 7;
        const float* s = Qb + (size_t)r*D_ + g8*8;
        float4 v = *(const float4*)s, w = *(const float4*)(s+4);
        int idx = r*Q_ST + g8*4;
        *(float4*)&Qs[idx]   = make_float4(to_tf32(v.x*0.125f),to_tf32(w.x*0.125f),
                                           to_tf32(v.y*0.125f),to_tf32(w.y*0.125f));
        *(float4*)&Qs[idx+2] = make_float4(to_tf32(v.z*0.125f),to_tf32(w.z*0.125f),
                                           to_tf32(v.w*0.125f),to_tf32(w.w*0.125f));
    }

    float m0=-3.4e38f, m1=-3.4e38f, l0=0.f, l1=0.f;
    float accO[8][4];
    #pragma unroll
    for(int i=0;i<8;i++){ accO[i][0]=0;accO[i][1]=0;accO[i][2]=0;accO[i][3]=0; }

    const int wrow = warp*16;
    const int ntiles = CAUSAL ? (qt+1) : 8;

    for(int kt=0; kt<ntiles; kt++){
        const float* Kt = Kb + (size_t)kt*128*D_;
        const float* Vt = Vb + (size_t)kt*128*D_;
        #pragma unroll
        for(int i=0;i<4;i++){
            int u = tid + i*256;
            int r = u >> 3, g8 = u & 7;
            const float* s = Kt + (size_t)r*D_ + g8*8;
            float4 v = *(const float4*)s, w = *(const float4*)(s+4);
            int idx = r*Q_ST + g8*4;
            *(float4*)&Ks[idx]   = make_float4(to_tf32(v.x),to_tf32(w.x),to_tf32(v.y),to_tf32(w.y));
            *(float4*)&Ks[idx+2] = make_float4(to_tf32(v.z),to_tf32(w.z),to_tf32(v.w),to_tf32(w.w));
        }
        #pragma unroll
        for(int i=0;i<4;i++){
            int u = tid + i*256;
            int pr = u >> 4, c4 = u & 15;
            int g8 = pr >> 2, tw = pr & 3;
            const float* s = Vt + (size_t)(g8*8 + tw)*D_ + c4*4;
            float4 v = *(const float4*)s, w = *(const float4*)(s + 4*(size_t)D_);
            int idx = pr*V_ST + c4*4;
            *(float4*)&Vs[idx]   = make_float4(to_tf32(v.x),to_tf32(w.x),to_tf32(v.y),to_tf32(w.y));
            *(float4*)&Vs[idx+2] = make_float4(to_tf32(v.z),to_tf32(w.z),to_tf32(v.w),to_tf32(w.w));
        }
        __syncthreads();

        float s[16][4];
        #pragma unroll
        for(int nt=0;nt<16;nt++){ s[nt][0]=0;s[nt][1]=0;s[nt][2]=0;s[nt][3]=0; }
        #pragma unroll
        for(int ks=0; ks<8; ks++){
            int q = ks*4 + tg;
            float2 a0 = Qs[(wrow+gid  )*Q_ST + q];
            float2 a1 = Qs[(wrow+gid+8)*Q_ST + q];
            uint32_t A0=fu(a0.x), A1=fu(a1.x), A2=fu(a0.y), A3=fu(a1.y);
            #pragma unroll
            for(int nt=0; nt<16; nt++){
                float2 bp = Ks[(nt*8+gid)*Q_ST + q];
                mma8(s[nt], A0, A1, A2, A3, fu(bp.x), fu(bp.y));
            }
        }

        const int gr0 = qt*128 + wrow + gid;
        const int gr1 = gr0 + 8;
        #pragma unroll
        for(int nt=0; nt<16; nt++){
            int gc = kt*128 + nt*8 + tg*2;
            if (CAUSAL){
                if (gc   > gr0) s[nt][0] += -1e9f;
                if (gc+1 > gr0) s[nt][1] += -1e9f;
                if (gc   > gr1) s[nt][2] += -1e9f;
                if (gc+1 > gr1) s[nt][3] += -1e9f;
            } else {
                const float* bp = bias + ((size_t)h*1024 + gr0)*1024 + gc;
                float2 b0 = *(const float2*)bp;
                float2 b1 = *(const float2*)(bp + 8*1024);
                s[nt][0]+=b0.x; s[nt][1]+=b0.y; s[nt][2]+=b1.x; s[nt][3]+=b1.y;
            }
        }

        float t0=-3.4e38f, t1=-3.4e38f;
        #pragma unroll
        for(int nt=0; nt<16; nt++){
            t0 = fmaxf(t0, fmaxf(s[nt][0], s[nt][1]));
            t1 = fmaxf(t1, fmaxf(s[nt][2], s[nt][3]));
        }
        t0 = fmaxf(t0, __shfl_xor_sync(0xffffffffu, t0, 1));
        t0 = fmaxf(t0, __shfl_xor_sync(0xffffffffu, t0, 2));
        t1 = fmaxf(t1, __shfl_xor_sync(0xffffffffu, t1, 1));
        t1 = fmaxf(t1, __shfl_xor_sync(0xffffffffu, t1, 2));
        float nm0 = fmaxf(m0, t0), nm1 = fmaxf(m1, t1);
        float c0 = __expf(m0 - nm0), c1 = __expf(m1 - nm1);
        float sum0 = 0.f, sum1 = 0.f;
        #pragma unroll
        for(int nt=0; nt<16; nt++){
            float p0 = __expf(s[nt][0]-nm0), p1 = __expf(s[nt][1]-nm0);
            float p2 = __expf(s[nt][2]-nm1), p3 = __expf(s[nt][3]-nm1);
            sum0 += p0+p1; sum1 += p2+p3;
            int c = nt*8 + tg*2;
            *(float2*)&Ps[(wrow+gid  )*P_ST + c] = make_float2(to_tf32(p0), to_tf32(p1));
            *(float2*)&Ps[(wrow+gid+8)*P_ST + c] = make_float2(to_tf32(p2), to_tf32(p3));
        }
        sum0 += __shfl_xor_sync(0xffffffffu, sum0, 1);
        sum0 += __shfl_xor_sync(0xffffffffu, sum0, 2);
        sum1 += __shfl_xor_sync(0xffffffffu, sum1, 1);
        sum1 += __shfl_xor_sync(0xffffffffu, sum1, 2);
        l0 = l0*c0 + sum0; l1 = l1*c1 + sum1;
        m0 = nm0; m1 = nm1;
        #pragma unroll
        for(int nt=0; nt<8; nt++){
            accO[nt][0]*=c0; accO[nt][1]*=c0; accO[nt][2]*=c1; accO[nt][3]*=c1;
        }
        __syncwarp();

        #pragma unroll
        for(int ks=0; ks<16; ks++){
            int k8 = ks*8;
            const float* pr0 = &Ps[(wrow+gid  )*P_ST + k8];
            const float* pr1 = &Ps[(wrow+gid+8)*P_ST + k8];
            uint32_t A0 = fu(pr0[tg]),   A1 = fu(pr1[tg]);
            uint32_t A2 = fu(pr0[tg+4]), A3 = fu(pr1[tg+4]);
            #pragma unroll
            for(int nt=0; nt<8; nt++){
                float2 bp = Vs[(ks*4+tg)*V_ST + nt*8 + gid];
                mma8(accO[nt], A0, A1, A2, A3, fu(bp.x), fu(bp.y));
            }
        }
        __syncthreads();
    }

    float inv0 = 1.f/l0, inv1 = 1.f/l1;
    int gq0 = b*1024 + qt*128 + wrow + gid;
    #pragma unroll
    for(int nt=0; nt<8; nt++){
        int c = h*64 + nt*8 + tg*2;
        *(float2*)(O + (size_t)gq0*D_ + c) =
            make_float2(accO[nt][0]*inv0, accO[nt][1]*inv0);
        *(float2*)(O + (size_t)(gq0+8)*D_ + c) =
            make_float2(accO[nt][2]*inv1, accO[nt][3]*inv1);
    }
}

// ---------------- host side ----------------
static void gemm1(const float* A, const float* W, float* C,
                  int M, int N, int K, const float* Add, bool relu){
    dim3 g(N/128, M/256, 1);
    if (relu)
        gemm_tc<true ><<<g,256,GEMM_SMEM>>>(A,A,A, W,W,W, C,C,C, Add, K, N);
    else
        gemm_tc<false><<<g,256,GEMM_SMEM>>>(A,A,A, W,W,W, C,C,C, Add, K, N);
}

static void gemm3(const float* A0,const float* A1,const float* A2,
                  const float* W0,const float* W1,const float* W2,
                  float* C0,float* C1,float* C2,
                  int M, int N, int K){
    dim3 g(N/128, M/256, 3);
    gemm_tc<false><<<g,256,GEMM_SMEM>>>(A0,A1,A2, W0,W1,W2, C0,C1,C2, nullptr, K, N);
}

extern "C" void kernel_launch(void* const* d_in, const int* in_sizes, int n_in,
                              void* d_out, int out_size)
{
    const float* x      = (const float*)d_in[0];
    const float* memin  = (const float*)d_in[1];
    const float* pos    = (const float*)d_in[2];
    // d_in[3] = causal mask (unused; computed analytically)
    const float* gsa    = (const float*)d_in[4];
    const float* wq_s   = (const float*)d_in[5];
    const float* wk_s   = (const float*)d_in[6];
    const float* wv_s   = (const float*)d_in[7];
    const float* wo_s   = (const float*)d_in[8];
    const float* gca    = (const float*)d_in[9];
    const float* wq_c   = (const float*)d_in[10];
    const float* wk_c   = (const float*)d_in[11];
    const float* wv_c   = (const float*)d_in[12];
    const float* wo_c   = (const float*)d_in[13];
    const float* gm     = (const float*)d_in[14];
    const float* w1     = (const float*)d_in[15];
    const float* w2     = (const float*)d_in[16];

    float* out     = (float*)d_out;
    float* out_mlp = out;
    float* out_ks  = out + (size_t)TENSOR_ELEMS;
    float* out_vs  = out + (size_t)TENSOR_ELEMS*2;
    float* out_kc  = out + (size_t)TENSOR_ELEMS*3;
    float* out_vc  = out + (size_t)TENSOR_ELEMS*4;

    float *h,*q,*k,*v,*m,*x1,*x2,*ffn;
    cudaGetSymbolAddress((void**)&h,   g_h);
    cudaGetSymbolAddress((void**)&q,   g_q);
    cudaGetSymbolAddress((void**)&k,   g_k);
    cudaGetSymbolAddress((void**)&v,   g_v);
    cudaGetSymbolAddress((void**)&m,   g_m);
    cudaGetSymbolAddress((void**)&x1,  g_x1);
    cudaGetSymbolAddress((void**)&x2,  g_x2);
    cudaGetSymbolAddress((void**)&ffn, g_ffn);

    cudaFuncSetAttribute(gemm_tc<false>, cudaFuncAttributeMaxDynamicSharedMemorySize, GEMM_SMEM);
    cudaFuncSetAttribute(gemm_tc<true >, cudaFuncAttributeMaxDynamicSharedMemorySize, GEMM_SMEM);
    cudaFuncSetAttribute(flash_k<true >, cudaFuncAttributeMaxDynamicSharedMemorySize, FLASH_SMEM);
    cudaFuncSetAttribute(flash_k<false>, cudaFuncAttributeMaxDynamicSharedMemorySize, FLASH_SMEM);

    // ============ self-attention block ============
    rmsnorm_k<<<MR_,256>>>(x, gsa, h);
    gemm3(h,h,h, wq_s,wk_s,wv_s, q,k,v, MR_, D_, D_);
    kvcopy2_k<<<dim3(4096,2),256>>>((const float4*)k, (float4*)out_ks,
                                    (const float4*)v, (float4*)out_vs);
    flash_k<true><<<dim3(8,64),256,FLASH_SMEM>>>(q, k, v, nullptr, m);
    gemm1(m, wo_s, x1, MR_, D_, D_, x, false);

    // ============ cross-attention block ============
    rmsnorm_k<<<MR_,256>>>(x1, gca, h);
    gemm3(h,memin,memin, wq_c,wk_c,wv_c, q,k,v, MR_, D_, D_);
    kvcopy2_k<<<dim3(4096,2),256>>>((const float4*)k, (float4*)out_kc,
                                    (const float4*)v, (float4*)out_vc);
    flash_k<false><<<dim3(8,64),256,FLASH_SMEM>>>(q, k, v, pos, m);
    gemm1(m, wo_c, x2, MR_, D_, D_, x1, false);

    // ============ FFN block ============
    rmsnorm_k<<<MR_,256>>>(x2, gm, h);
    gemm1(h, w1, ffn, MR_, F_, D_, nullptr, true);
    gemm1(ffn, w2, out_mlp, MR_, D_, F_, x2, false);
}

// round 17
// speedup vs baseline: 1.5669x; 1.0455x over previous
#include <cuda_runtime.h>
#include <stdint.h>

// ---------------- problem constants ----------------
#define B_   4
#define LT_  1024
#define D_   1024
#define H_   16
#define HD_  64
#define F_   4096
#define MR_  (B_*LT_)     // 4096 rows
#define TENSOR_ELEMS (MR_*D_)  // 4194304

// ---------------- scratch (device globals; no allocs allowed) ----------------
__device__ float g_h  [MR_*D_];          // normed activations (tf32-rounded)
__device__ float g_q  [MR_*D_];
__device__ float g_k  [MR_*D_];
__device__ float g_v  [MR_*D_];
__device__ float g_m  [MR_*D_];          // merged attention output (tf32-rounded)
__device__ float g_x1 [MR_*D_];          // attn_x
__device__ float g_x2 [MR_*D_];          // cross_x
__device__ float g_ffn[MR_*F_];          // relu(h@w1) (tf32-rounded)
__device__ float g_w  [20*1024*1024];    // pre-converted weights + memory (80MB)

// offsets (floats) into g_w
#define OW_QS  (0ull)
#define OW_KS  (1ull*1024*1024)
#define OW_VS  (2ull*1024*1024)
#define OW_OS  (3ull*1024*1024)
#define OW_QC  (4ull*1024*1024)
#define OW_KC  (5ull*1024*1024)
#define OW_VC  (6ull*1024*1024)
#define OW_OC  (7ull*1024*1024)
#define OW_1   (8ull*1024*1024)
#define OW_2   (12ull*1024*1024)
#define OW_MEM (16ull*1024*1024)

// ---------------- helpers ----------------
__device__ __forceinline__ float to_tf32(float x){
    uint32_t u; asm("cvt.rna.tf32.f32 %0, %1;" : "=r"(u) : "f"(x));
    return __uint_as_float(u);
}
__device__ __forceinline__ uint32_t fu(float x){ return __float_as_uint(x); }

__device__ __forceinline__ void mma8(float* c,
    uint32_t a0, uint32_t a1, uint32_t a2, uint32_t a3,
    uint32_t b0, uint32_t b1){
    asm volatile(
        "mma.sync.aligned.m16n8k8.row.col.f32.tf32.tf32.f32 "
        "{%0,%1,%2,%3}, {%4,%5,%6,%7}, {%8,%9}, {%0,%1,%2,%3};\n"
        : "+f"(c[0]), "+f"(c[1]), "+f"(c[2]), "+f"(c[3])
        : "r"(a0), "r"(a1), "r"(a2), "r"(a3), "r"(b0), "r"(b1));
}

__device__ __forceinline__ float blockReduceSum(float v){
    __shared__ float red[8];
    int lane = threadIdx.x & 31, w = threadIdx.x >> 5;
    #pragma unroll
    for(int o=16;o>0;o>>=1) v += __shfl_xor_sync(0xffffffffu, v, o);
    if(lane==0) red[w]=v;
    __syncthreads();
    float s = (threadIdx.x < 8) ? red[threadIdx.x] : 0.f;
    if(w==0){
        #pragma unroll
        for(int o=4;o>0;o>>=1) s += __shfl_xor_sync(0xffffffffu, s, o);
        if(lane==0) red[0]=s;
    }
    __syncthreads();
    float out = red[0];
    __syncthreads();
    return out;
}

// ---------------- pre-convert weights + memory to tf32 ----------------
__global__ void preconv_k(
    const float4* a0, const float4* a1, const float4* a2, const float4* a3,
    const float4* a4, const float4* a5, const float4* a6, const float4* a7,
    const float4* a8, const float4* a9, const float4* a10, float4* dst)
{
    int z = blockIdx.y;
    const float4* src; size_t off; int n;  // n in float4
    switch(z){
        case 0:  src=a0;  off=OW_QS/4;  n=262144;  break;
        case 1:  src=a1;  off=OW_KS/4;  n=262144;  break;
        case 2:  src=a2;  off=OW_VS/4;  n=262144;  break;
        case 3:  src=a3;  off=OW_OS/4;  n=262144;  break;
        case 4:  src=a4;  off=OW_QC/4;  n=262144;  break;
        case 5:  src=a5;  off=OW_KC/4;  n=262144;  break;
        case 6:  src=a6;  off=OW_VC/4;  n=262144;  break;
        case 7:  src=a7;  off=OW_OC/4;  n=262144;  break;
        case 8:  src=a8;  off=OW_1/4;   n=1048576; break;
        case 9:  src=a9;  off=OW_2/4;   n=1048576; break;
        default: src=a10; off=OW_MEM/4; n=1048576; break;
    }
    int i = blockIdx.x*256 + threadIdx.x;
    if (i < n){
        float4 v = src[i];
        dst[off+i] = make_float4(to_tf32(v.x),to_tf32(v.y),to_tf32(v.z),to_tf32(v.w));
    }
}

// ---------------- RMS norm (emits tf32-rounded output) ----------------
__global__ void rmsnorm_k(const float* __restrict__ x, const float* __restrict__ g,
                          float* __restrict__ o){
    int row = blockIdx.x; int tid = threadIdx.x;
    const float4* xr = (const float4*)(x + (size_t)row*D_);
    float4 v = xr[tid];
    float ss = v.x*v.x + v.y*v.y + v.z*v.z + v.w*v.w;
    ss = blockReduceSum(ss);
    float scale = rsqrtf(ss * (1.0f/D_) + 1e-6f);
    float4 gv = ((const float4*)g)[tid];
    float4 r;
    r.x = to_tf32(v.x*scale*gv.x); r.y = to_tf32(v.y*scale*gv.y);
    r.z = to_tf32(v.z*scale*gv.z); r.w = to_tf32(v.w*scale*gv.w);
    ((float4*)(o + (size_t)row*D_))[tid] = r;
}

// ---------------- [B*L, H*HD] -> [B,H,L,HD] transpose copy (x2 batched) ----------------
__global__ void kvcopy2_k(const float4* __restrict__ in0, float4* __restrict__ o0,
                          const float4* __restrict__ in1, float4* __restrict__ o1){
    int idx = blockIdx.x*256 + threadIdx.x;
    const float4* in = blockIdx.y ? in1 : in0;
    float4*      out = blockIdx.y ? o1  : o0;
    int hd4 = idx & 15;
    int h   = (idx >> 4) & 15;
    int l   = (idx >> 8) & 1023;
    int b   = idx >> 18;
    out[(((size_t)(b*16 + h)*1024 + l) << 4) + hd4] =
        in[(((size_t)(b*1024 + l)) << 8) + h*16 + hd4];
}

// =====================================================================
// tf32 tensor-core GEMM, NN. CTA tile 256x128, BK=32, 8 warps (4x2),
// warp tile 64x64. Pair-packed smem, zero cvt (inputs pre-rounded).
// =====================================================================
#define A_ST  20              // float2 stride of A smem row (16 + 4 pad)
#define A_SZ  (256*A_ST)
#define B_ST  132             // float2 stride of B smem row (128 + 4 pad)
#define B_SZ  (16*B_ST)
static const int GEMM_SMEM = (2*A_SZ + 2*B_SZ)*8;

template<bool RELU, bool TF32OUT>
__global__ void __launch_bounds__(256,1) gemm_tc(
    const float* __restrict__ A0, const float* __restrict__ A1, const float* __restrict__ A2,
    const float* __restrict__ W0, const float* __restrict__ W1, const float* __restrict__ W2,
    float* __restrict__ C0, float* __restrict__ C1, float* __restrict__ C2,
    const float* __restrict__ Add,
    int K, int N)
{
    extern __shared__ float2 sm2[];
    float2* As = sm2;                  // [2][256][A_ST]
    float2* Bs = sm2 + 2*A_SZ;         // [2][16][B_ST]

    const int tid  = threadIdx.x;
    const int lane = tid & 31, warp = tid >> 5;
    const int wm = warp & 3, wn = warp >> 2;
    const int gid = lane >> 2, tg = lane & 3;

    const int z = blockIdx.z;
    const float* A  = (z==0) ? A0 : (z==1) ? A1 : A2;
    const float* Bm = (z==0) ? W0 : (z==1) ? W1 : W2;
    float*       C  = (z==0) ? C0 : (z==1) ? C1 : C2;

    A  += (size_t)blockIdx.y*256*K;
    Bm += (size_t)blockIdx.x*128;
    C  += (size_t)blockIdx.y*256*N + (size_t)blockIdx.x*128;
    if (Add) Add += (size_t)blockIdx.y*256*N + (size_t)blockIdx.x*128;

    float acc[4][8][4];
    #pragma unroll
    for(int i=0;i<4;i++)
        #pragma unroll
        for(int j=0;j<8;j++)
            #pragma unroll
            for(int e=0;e<4;e++) acc[i][j][e]=0.f;

    float4 rA[4][2], rB[2][2];

    auto loadA = [&](int kt){
        #pragma unroll
        for(int i=0;i<4;i++){
            int u = tid + i*256;
            int r = u >> 2, g8 = u & 3;
            const float* s = A + (size_t)r*K + kt*32 + g8*8;
            rA[i][0] = *(const float4*)s;
            rA[i][1] = *(const float4*)(s+4);
        }
    };
    auto storeA = [&](int buf){
        #pragma unroll
        for(int i=0;i<4;i++){
            int u = tid + i*256;
            int r = u >> 2, g8 = u & 3;
            float4 v = rA[i][0], w = rA[i][1];
            int idx = buf*A_SZ + r*A_ST + g8*4;
            *(float4*)&As[idx]   = make_float4(v.x,w.x,v.y,w.y);
            *(float4*)&As[idx+2] = make_float4(v.z,w.z,v.w,w.w);
        }
    };
    auto loadB = [&](int kt){
        #pragma unroll
        for(int i=0;i<2;i++){
            int u = tid + i*256;
            int pr = u >> 5, c4 = u & 31;
            int g8 = pr >> 2, tw = pr & 3;
            const float* s = Bm + (size_t)(kt*32 + g8*8 + tw)*N + c4*4;
            rB[i][0] = *(const float4*)s;
            rB[i][1] = *(const float4*)(s + 4*(size_t)N);
        }
    };
    auto storeB = [&](int buf){
        #pragma unroll
        for(int i=0;i<2;i++){
            int u = tid + i*256;
            int pr = u >> 5, c4 = u & 31;
            float4 v = rB[i][0], w = rB[i][1];
            int idx = buf*B_SZ + pr*B_ST + c4*4;
            *(float4*)&Bs[idx]   = make_float4(v.x,w.x,v.y,w.y);
            *(float4*)&Bs[idx+2] = make_float4(v.z,w.z,v.w,w.w);
        }
    };
    auto compute = [&](int buf){
        #pragma unroll
        for(int ks=0; ks<4; ks++){
            const int q = ks*4 + tg;
            float2 a[4][2];
            #pragma unroll
            for(int mt=0; mt<4; mt++){
                int row = wm*64 + mt*16;
                a[mt][0] = As[buf*A_SZ + (row+gid  )*A_ST + q];
                a[mt][1] = As[buf*A_SZ + (row+gid+8)*A_ST + q];
            }
            float2 bb[8];
            #pragma unroll
            for(int nt=0; nt<8; nt++){
                int col = wn*64 + nt*8 + gid;
                bb[nt] = Bs[buf*B_SZ + q*B_ST + col];
            }
            #pragma unroll
            for(int mt=0; mt<4; mt++)
                #pragma unroll
                for(int nt=0; nt<8; nt++)
                    mma8(acc[mt][nt],
                         fu(a[mt][0].x), fu(a[mt][1].x), fu(a[mt][0].y), fu(a[mt][1].y),
                         fu(bb[nt].x), fu(bb[nt].y));
        }
    };

    const int nT = K / 32;
    loadA(0); loadB(0);
    storeA(0); storeB(0);
    __syncthreads();
    for(int t=0; t<nT; t++){
        const int cur = t & 1;
        if (t+1 < nT){ loadA(t+1); loadB(t+1); }
        compute(cur);
        if (t+1 < nT){ storeA(cur^1); storeB(cur^1); }
        __syncthreads();
    }

    #pragma unroll
    for(int mt=0; mt<4; mt++)
        #pragma unroll
        for(int nt=0; nt<8; nt++){
            int row0 = wm*64 + mt*16 + gid;
            int col0 = wn*64 + nt*8 + tg*2;
            #pragma unroll
            for(int half=0; half<2; half++){
                int r = row0 + half*8;
                float v0 = acc[mt][nt][half*2+0];
                float v1 = acc[mt][nt][half*2+1];
                if (Add){
                    v0 += Add[(size_t)r*N + col0];
                    v1 += Add[(size_t)r*N + col0 + 1];
                }
                if (RELU){ v0 = fmaxf(v0,0.f); v1 = fmaxf(v1,0.f); }
                if (TF32OUT){ v0 = to_tf32(v0); v1 = to_tf32(v1); }
                *(float2*)(C + (size_t)r*N + col0) = make_float2(v0, v1);
            }
        }
}

// =====================================================================
// Flash attention (tf32): per CTA one (b,h,q-tile of 128). 8 warps x 16 rows.
// Register double-buffered K/V prefetch. Emits tf32-rounded O.
// =====================================================================
#define Q_ST 36               // float2 stride (32 + 4 pad, conflict-free LDS.64)
#define V_ST 68
#define P_ST 132
#define OFF_KS  (128*Q_ST)           // float2 offsets
#define OFF_VS  (2*128*Q_ST)
#define OFF_PS_BYTES ((2*128*Q_ST + 64*V_ST)*8)
#define FLASH_SMEM (OFF_PS_BYTES + 128*P_ST*4)

template<bool CAUSAL>
__global__ void __launch_bounds__(256) flash_k(
    const float* __restrict__ Q, const float* __restrict__ Kg,
    const float* __restrict__ Vg, const float* __restrict__ bias,
    float* __restrict__ O)
{
    extern __shared__ float2 sm2[];
    float2* Qs = sm2;
    float2* Ks = sm2 + OFF_KS;
    float2* Vs = sm2 + OFF_VS;
    float*  Ps = (float*)((char*)sm2 + OFF_PS_BYTES);

    const int tid = threadIdx.x, lane = tid & 31, warp = tid >> 5;
    const int gid = lane >> 2, tg = lane & 3;
    const int qt = blockIdx.x, bh = blockIdx.y;
    const int b = bh >> 4, h = bh & 15;

    const float* Qb = Q  + ((size_t)(b*1024 + qt*128))*D_ + h*64;
    const float* Kb = Kg + ((size_t)b*1024)*D_ + h*64;
    const float* Vb = Vg + ((size_t)b*1024)*D_ + h*64;

    // load Q tile (scaled by 1/8, tf32), A-pack
    #pragma unroll
    for(int i=0;i<4;i++){
        int u = tid + i*256;
        int r = u >> 3, g8 = u & 7;
        const float* s = Qb + (size_t)r*D_ + g8*8;
        float4 v = *(const float4*)s, w = *(const float4*)(s+4);
        int idx = r*Q_ST + g8*4;
        *(float4*)&Qs[idx]   = make_float4(to_tf32(v.x*0.125f),to_tf32(w.x*0.125f),
                                           to_tf32(v.y*0.125f),to_tf32(w.y*0.125f));
        *(float4*)&Qs[idx+2] = make_float4(to_tf32(v.z*0.125f),to_tf32(w.z*0.125f),
                                           to_tf32(v.w*0.125f),to_tf32(w.w*0.125f));
    }

    float m0=-3.4e38f, m1=-3.4e38f, l0=0.f, l1=0.f;
    float accO[8][4];
    #pragma unroll
    for(int i=0;i<8;i++){ accO[i][0]=0;accO[i][1]=0;accO[i][2]=0;accO[i][3]=0; }

    const int wrow = warp*16;
    const int ntiles = CAUSAL ? (qt+1) : 8;

    // K/V prefetch registers
    float4 pK[4][2], pV[4][2];
    auto prefetchKV = [&](int kt){
        const float* Kt = Kb + (size_t)kt*128*D_;
        #pragma unroll
        for(int i=0;i<4;i++){
            int u = tid + i*256;
            int r = u >> 3, g8 = u & 7;
            const float* s = Kt + (size_t)r*D_ + g8*8;
            pK[i][0] = *(const float4*)s;
            pK[i][1] = *(const float4*)(s+4);
        }
        const float* Vt = Vb + (size_t)kt*128*D_;
        #pragma unroll
        for(int i=0;i<4;i++){
            int u = tid + i*256;
            int pr = u >> 4, c4 = u & 15;
            int g8 = pr >> 2, tw = pr & 3;
            const float* s = Vt + (size_t)(g8*8 + tw)*D_ + c4*4;
            pV[i][0] = *(const float4*)s;
            pV[i][1] = *(const float4*)(s + 4*(size_t)D_);
        }
    };
    auto storeKV = [&](){
        #pragma unroll
        for(int i=0;i<4;i++){
            int u = tid + i*256;
            int r = u >> 3, g8 = u & 7;
            float4 v = pK[i][0], w = pK[i][1];
            int idx = r*Q_ST + g8*4;
            *(float4*)&Ks[idx]   = make_float4(to_tf32(v.x),to_tf32(w.x),to_tf32(v.y),to_tf32(w.y));
            *(float4*)&Ks[idx+2] = make_float4(to_tf32(v.z),to_tf32(w.z),to_tf32(v.w),to_tf32(w.w));
        }
        #pragma unroll
        for(int i=0;i<4;i++){
            int u = tid + i*256;
            int pr = u >> 4, c4 = u & 15;
            float4 v = pV[i][0], w = pV[i][1];
            int idx = pr*V_ST + c4*4;
            *(float4*)&Vs[idx]   = make_float4(to_tf32(v.x),to_tf32(w.x),to_tf32(v.y),to_tf32(w.y));
            *(float4*)&Vs[idx+2] = make_float4(to_tf32(v.z),to_tf32(w.z),to_tf32(v.w),to_tf32(w.w));
        }
    };

    prefetchKV(0);
    for(int kt=0; kt<ntiles; kt++){
        storeKV();
        __syncthreads();
        if (kt+1 < ntiles) prefetchKV(kt+1);

        // ---- S = Qs @ Ks^T ----
        float s[16][4];
        #pragma unroll
        for(int nt=0;nt<16;nt++){ s[nt][0]=0;s[nt][1]=0;s[nt][2]=0;s[nt][3]=0; }
        #pragma unroll
        for(int ks=0; ks<8; ks++){
            int q = ks*4 + tg;
            float2 a0 = Qs[(wrow+gid  )*Q_ST + q];
            float2 a1 = Qs[(wrow+gid+8)*Q_ST + q];
            uint32_t A0=fu(a0.x), A1=fu(a1.x), A2=fu(a0.y), A3=fu(a1.y);
            #pragma unroll
            for(int nt=0; nt<16; nt++){
                float2 bp = Ks[(nt*8+gid)*Q_ST + q];
                mma8(s[nt], A0, A1, A2, A3, fu(bp.x), fu(bp.y));
            }
        }

        // ---- bias / causal mask ----
        const int gr0 = qt*128 + wrow + gid;
        const int gr1 = gr0 + 8;
        #pragma unroll
        for(int nt=0; nt<16; nt++){
            int gc = kt*128 + nt*8 + tg*2;
            if (CAUSAL){
                if (gc   > gr0) s[nt][0] += -1e9f;
                if (gc+1 > gr0) s[nt][1] += -1e9f;
                if (gc   > gr1) s[nt][2] += -1e9f;
                if (gc+1 > gr1) s[nt][3] += -1e9f;
            } else {
                const float* bp = bias + ((size_t)h*1024 + gr0)*1024 + gc;
                float2 b0 = *(const float2*)bp;
                float2 b1 = *(const float2*)(bp + 8*1024);
                s[nt][0]+=b0.x; s[nt][1]+=b0.y; s[nt][2]+=b1.x; s[nt][3]+=b1.y;
            }
        }

        // ---- online softmax ----
        float t0=-3.4e38f, t1=-3.4e38f;
        #pragma unroll
        for(int nt=0; nt<16; nt++){
            t0 = fmaxf(t0, fmaxf(s[nt][0], s[nt][1]));
            t1 = fmaxf(t1, fmaxf(s[nt][2], s[nt][3]));
        }
        t0 = fmaxf(t0, __shfl_xor_sync(0xffffffffu, t0, 1));
        t0 = fmaxf(t0, __shfl_xor_sync(0xffffffffu, t0, 2));
        t1 = fmaxf(t1, __shfl_xor_sync(0xffffffffu, t1, 1));
        t1 = fmaxf(t1, __shfl_xor_sync(0xffffffffu, t1, 2));
        float nm0 = fmaxf(m0, t0), nm1 = fmaxf(m1, t1);
        float c0 = __expf(m0 - nm0), c1 = __expf(m1 - nm1);
        float sum0 = 0.f, sum1 = 0.f;
        #pragma unroll
        for(int nt=0; nt<16; nt++){
            float p0 = __expf(s[nt][0]-nm0), p1 = __expf(s[nt][1]-nm0);
            float p2 = __expf(s[nt][2]-nm1), p3 = __expf(s[nt][3]-nm1);
            sum0 += p0+p1; sum1 += p2+p3;
            int c = nt*8 + tg*2;
            *(float2*)&Ps[(wrow+gid  )*P_ST + c] = make_float2(to_tf32(p0), to_tf32(p1));
            *(float2*)&Ps[(wrow+gid+8)*P_ST + c] = make_float2(to_tf32(p2), to_tf32(p3));
        }
        sum0 += __shfl_xor_sync(0xffffffffu, sum0, 1);
        sum0 += __shfl_xor_sync(0xffffffffu, sum0, 2);
        sum1 += __shfl_xor_sync(0xffffffffu, sum1, 1);
        sum1 += __shfl_xor_sync(0xffffffffu, sum1, 2);
        l0 = l0*c0 + sum0; l1 = l1*c1 + sum1;
        m0 = nm0; m1 = nm1;
        #pragma unroll
        for(int nt=0; nt<8; nt++){
            accO[nt][0]*=c0; accO[nt][1]*=c0; accO[nt][2]*=c1; accO[nt][3]*=c1;
        }
        __syncwarp();

        // ---- O += P @ V ----
        #pragma unroll
        for(int ks=0; ks<16; ks++){
            int k8 = ks*8;
            const float* pr0 = &Ps[(wrow+gid  )*P_ST + k8];
            const float* pr1 = &Ps[(wrow+gid+8)*P_ST + k8];
            uint32_t A0 = fu(pr0[tg]),   A1 = fu(pr1[tg]);
            uint32_t A2 = fu(pr0[tg+4]), A3 = fu(pr1[tg+4]);
            #pragma unroll
            for(int nt=0; nt<8; nt++){
                float2 bp = Vs[(ks*4+tg)*V_ST + nt*8 + gid];
                mma8(accO[nt], A0, A1, A2, A3, fu(bp.x), fu(bp.y));
            }
        }
        __syncthreads();
    }

    // ---- epilogue: O / l (tf32-rounded; feeds wo GEMM) ----
    float inv0 = 1.f/l0, inv1 = 1.f/l1;
    int gq0 = b*1024 + qt*128 + wrow + gid;
    #pragma unroll
    for(int nt=0; nt<8; nt++){
        int c = h*64 + nt*8 + tg*2;
        *(float2*)(O + (size_t)gq0*D_ + c) =
            make_float2(to_tf32(accO[nt][0]*inv0), to_tf32(accO[nt][1]*inv0));
        *(float2*)(O + (size_t)(gq0+8)*D_ + c) =
            make_float2(to_tf32(accO[nt][2]*inv1), to_tf32(accO[nt][3]*inv1));
    }
}

// ---------------- host side ----------------
static void gemm1(const float* A, const float* W, float* C,
                  int M, int N, int K, const float* Add, bool relu_tf32){
    dim3 g(N/128, M/256, 1);
    if (relu_tf32)
        gemm_tc<true ,true ><<<g,256,GEMM_SMEM>>>(A,A,A, W,W,W, C,C,C, Add, K, N);
    else
        gemm_tc<false,false><<<g,256,GEMM_SMEM>>>(A,A,A, W,W,W, C,C,C, Add, K, N);
}

static void gemm3(const float* A0,const float* A1,const float* A2,
                  const float* W0,const float* W1,const float* W2,
                  float* C0,float* C1,float* C2,
                  int M, int N, int K){
    dim3 g(N/128, M/256, 3);
    gemm_tc<false,false><<<g,256,GEMM_SMEM>>>(A0,A1,A2, W0,W1,W2, C0,C1,C2, nullptr, K, N);
}

extern "C" void kernel_launch(void* const* d_in, const int* in_sizes, int n_in,
                              void* d_out, int out_size)
{
    const float* x      = (const float*)d_in[0];
    const float* memin  = (const float*)d_in[1];
    const float* pos    = (const float*)d_in[2];
    // d_in[3] = causal mask (unused; computed analytically)
    const float* gsa    = (const float*)d_in[4];
    const float* gca    = (const float*)d_in[9];
    const float* gm     = (const float*)d_in[14];

    float* out     = (float*)d_out;
    float* out_mlp = out;
    float* out_ks  = out + (size_t)TENSOR_ELEMS;
    float* out_vs  = out + (size_t)TENSOR_ELEMS*2;
    float* out_kc  = out + (size_t)TENSOR_ELEMS*3;
    float* out_vc  = out + (size_t)TENSOR_ELEMS*4;

    float *h,*q,*k,*v,*m,*x1,*x2,*ffn,*w;
    cudaGetSymbolAddress((void**)&h,   g_h);
    cudaGetSymbolAddress((void**)&q,   g_q);
    cudaGetSymbolAddress((void**)&k,   g_k);
    cudaGetSymbolAddress((void**)&v,   g_v);
    cudaGetSymbolAddress((void**)&m,   g_m);
    cudaGetSymbolAddress((void**)&x1,  g_x1);
    cudaGetSymbolAddress((void**)&x2,  g_x2);
    cudaGetSymbolAddress((void**)&ffn, g_ffn);
    cudaGetSymbolAddress((void**)&w,   g_w);

    cudaFuncSetAttribute(gemm_tc<false,false>, cudaFuncAttributeMaxDynamicSharedMemorySize, GEMM_SMEM);
    cudaFuncSetAttribute(gemm_tc<true ,true >, cudaFuncAttributeMaxDynamicSharedMemorySize, GEMM_SMEM);
    cudaFuncSetAttribute(flash_k<true >, cudaFuncAttributeMaxDynamicSharedMemorySize, FLASH_SMEM);
    cudaFuncSetAttribute(flash_k<false>, cudaFuncAttributeMaxDynamicSharedMemorySize, FLASH_SMEM);

    // ---- pre-convert weights + memory to tf32 (once per launch) ----
    preconv_k<<<dim3(4096,11),256>>>(
        (const float4*)d_in[5],  (const float4*)d_in[6],  (const float4*)d_in[7],
        (const float4*)d_in[8],  (const float4*)d_in[10], (const float4*)d_in[11],
        (const float4*)d_in[12], (const float4*)d_in[13], (const float4*)d_in[15],
        (const float4*)d_in[16], (const float4*)memin, (float4*)w);

    const float* wq_s = w + OW_QS;  const float* wk_s = w + OW_KS;
    const float* wv_s = w + OW_VS;  const float* wo_s = w + OW_OS;
    const float* wq_c = w + OW_QC;  const float* wk_c = w + OW_KC;
    const float* wv_c = w + OW_VC;  const float* wo_c = w + OW_OC;
    const float* w1   = w + OW_1;   const float* w2   = w + OW_2;
    const float* memc = w + OW_MEM;

    // ============ self-attention block ============
    rmsnorm_k<<<MR_,256>>>(x, gsa, h);
    gemm3(h,h,h, wq_s,wk_s,wv_s, q,k,v, MR_, D_, D_);
    kvcopy2_k<<<dim3(4096,2),256>>>((const float4*)k, (float4*)out_ks,
                                    (const float4*)v, (float4*)out_vs);
    flash_k<true><<<dim3(8,64),256,FLASH_SMEM>>>(q, k, v, nullptr, m);
    gemm1(m, wo_s, x1, MR_, D_, D_, x, false);

    // ============ cross-attention block ============
    rmsnorm_k<<<MR_,256>>>(x1, gca, h);
    gemm3(h,memc,memc, wq_c,wk_c,wv_c, q,k,v, MR_, D_, D_);
    kvcopy2_k<<<dim3(4096,2),256>>>((const float4*)k, (float4*)out_kc,
                                    (const float4*)v, (float4*)out_vc);
    flash_k<false><<<dim3(8,64),256,FLASH_SMEM>>>(q, k, v, pos, m);
    gemm1(m, wo_c, x2, MR_, D_, D_, x1, false);

    // ============ FFN block ============
    rmsnorm_k<<<MR_,256>>>(x2, gm, h);
    gemm1(h, w1, ffn, MR_, F_, D_, nullptr, true);
    gemm1(ffn, w2, out_mlp, MR_, D_, F_, x2, false);
}